// round 4
// baseline (speedup 1.0000x reference)
#include <cuda_runtime.h>

#define D_MODEL 512
#define KEY_DIM 128
#define BS_N 16
#define CTX_PER 1024
#define ARGS_PER 32
#define N_ARGS (BS_N * ARGS_PER)      /* 512  */
#define N_CTX  (BS_N * CTX_PER)       /* 16384 */
#define P_TOT  (N_ARGS * CTX_PER)     /* 524288 */

// Scratch (allocation-free rule: device globals). Accessed ONLY from device
// code -- passing these as host-side kernel args yields the host shadow
// symbol (and ATS happily reads host zeros). That was the R3 bug.
__device__ float g_Qp[N_ARGS * D_MODEL];   // Qp[r,d] = sum_k arg[r,k] * W[d,k]
__device__ float g_qb[N_ARGS];             // qb[r]   = arg[r,:] . b

// ---------------------------------------------------------------------------
// Packed fp32x2 FMA: lanes = two output ROWS. No broadcast movs needed:
// a-operand comes straight from transposed Q smem (LDS.64), b-operand from a
// duplicated C tile (each value stored as (v,v)).
// ---------------------------------------------------------------------------
__device__ __forceinline__ void ffma2(unsigned long long& d,
                                      unsigned long long a,
                                      unsigned long long b) {
    asm("fma.rn.f32x2 %0, %1, %2, %0;" : "+l"(d) : "l"(a), "l"(b));
}
__device__ __forceinline__ float2 unpack2(unsigned long long v) {
    float2 f;
    asm("mov.b64 {%0, %1}, %2;" : "=f"(f.x), "=f"(f.y) : "l"(v));
    return f;
}

// ---------------------------------------------------------------------------
// Unified GEMM: out[32 x TILE_N] tile of  Qrows[32,KD] @ Crows[TILE_N,KD]^T
//   256 threads: ty = tid>>4 (0..15) -> packed row pair (2ty, 2ty+1)
//                tx = tid&15         -> cols tx + 16*j, j = 0..TILE_N/16-1
// Double-buffered smem, ONE __syncthreads per K-chunk.
//   Qs[buf][k][row]        (row pairs read as 64-bit)
//   Cs[buf][k][2c]=(v,v)   (dup store -> broadcast-free LDS.64, bank-clean)
// LOGITS: Q source is g_Qp (device symbol), adds g_qb[row], writes rows plane.
// !LOGITS: Q source is param Qm (arg_values), writes g_Qp.
// ---------------------------------------------------------------------------
template<int KD, int TILE_N, bool LOGITS>
__global__ __launch_bounds__(256) void gemm_kernel(const float* __restrict__ Qm,
                                                   const float* __restrict__ Cm,
                                                   float* __restrict__ out,
                                                   float* __restrict__ rows_out) {
    constexpr int NCH = KD / 32;          // K chunks
    constexpr int NJ  = TILE_N / 16;      // packed accumulators per thread
    constexpr int CPT = TILE_N / 32;      // C float4 loads per thread per chunk
    constexpr int QW  = 34;               // Qs row stride (floats)
    constexpr int CW  = TILE_N * 2 + 2;   // Cs row stride (floats), 8B-aligned

    __shared__ __align__(16) float Qs[2][32][QW];
    __shared__ __align__(16) float Cs[2][32][CW];

    const int tid = threadIdx.x;
    const int ty = tid >> 4, tx = tid & 15;

    const float* Qsrc_base = LOGITS ? (const float*)g_Qp : Qm;

    const int qrow_base = blockIdx.y * 32;                        // Q row tile
    const int crow_base = (LOGITS ? blockIdx.y * CTX_PER : 0)     // C row tile
                        + blockIdx.x * TILE_N;

    // loader indices
    const int lq_row = tid >> 3;               // 0..31
    const int lq_k   = (tid & 7) * 4;
    const float* qsrc = Qsrc_base + (size_t)(qrow_base + lq_row) * KD + lq_k;

    int lc_row[CPT], lc_k[CPT];
    const float* csrc[CPT];
    #pragma unroll
    for (int jj = 0; jj < CPT; jj++) {
        int id = tid + jj * 256;
        lc_row[jj] = id >> 3;                  // 0..TILE_N-1
        lc_k[jj]   = (id & 7) * 4;
        csrc[jj] = Cm + (size_t)(crow_base + lc_row[jj]) * KD + lc_k[jj];
    }

    unsigned long long acc[NJ];
    #pragma unroll
    for (int j = 0; j < NJ; j++) acc[j] = 0ull;

    // ---- prologue: chunk 0 into buffer 0
    {
        float4 q = *(const float4*)qsrc;
        Qs[0][lq_k + 0][lq_row] = q.x; Qs[0][lq_k + 1][lq_row] = q.y;
        Qs[0][lq_k + 2][lq_row] = q.z; Qs[0][lq_k + 3][lq_row] = q.w;
        #pragma unroll
        for (int jj = 0; jj < CPT; jj++) {
            float4 c = *(const float4*)csrc[jj];
            *(float2*)&Cs[0][lc_k[jj] + 0][2 * lc_row[jj]] = make_float2(c.x, c.x);
            *(float2*)&Cs[0][lc_k[jj] + 1][2 * lc_row[jj]] = make_float2(c.y, c.y);
            *(float2*)&Cs[0][lc_k[jj] + 2][2 * lc_row[jj]] = make_float2(c.z, c.z);
            *(float2*)&Cs[0][lc_k[jj] + 3][2 * lc_row[jj]] = make_float2(c.w, c.w);
        }
    }
    __syncthreads();

    #pragma unroll 1
    for (int it = 0; it < NCH; it++) {
        const int buf = it & 1;

        // prefetch next chunk to registers (overlaps with compute below)
        float4 qn;
        float4 cn[CPT];
        if (it + 1 < NCH) {
            qn = *(const float4*)(qsrc + (it + 1) * 32);
            #pragma unroll
            for (int jj = 0; jj < CPT; jj++)
                cn[jj] = *(const float4*)(csrc[jj] + (it + 1) * 32);
        }

        // compute current chunk
        #pragma unroll
        for (int k = 0; k < 32; k++) {
            unsigned long long qp =
                *(const unsigned long long*)&Qs[buf][k][2 * ty];
            #pragma unroll
            for (int j = 0; j < NJ; j++) {
                unsigned long long cp =
                    *(const unsigned long long*)&Cs[buf][k][2 * (tx + 16 * j)];
                ffma2(acc[j], qp, cp);
            }
        }

        // store next chunk into other buffer
        if (it + 1 < NCH) {
            const int nb = buf ^ 1;
            Qs[nb][lq_k + 0][lq_row] = qn.x; Qs[nb][lq_k + 1][lq_row] = qn.y;
            Qs[nb][lq_k + 2][lq_row] = qn.z; Qs[nb][lq_k + 3][lq_row] = qn.w;
            #pragma unroll
            for (int jj = 0; jj < CPT; jj++) {
                *(float2*)&Cs[nb][lc_k[jj] + 0][2 * lc_row[jj]] = make_float2(cn[jj].x, cn[jj].x);
                *(float2*)&Cs[nb][lc_k[jj] + 1][2 * lc_row[jj]] = make_float2(cn[jj].y, cn[jj].y);
                *(float2*)&Cs[nb][lc_k[jj] + 2][2 * lc_row[jj]] = make_float2(cn[jj].z, cn[jj].z);
                *(float2*)&Cs[nb][lc_k[jj] + 3][2 * lc_row[jj]] = make_float2(cn[jj].w, cn[jj].w);
            }
            __syncthreads();
        }
    }

    // ---- epilogue
    const int r0 = qrow_base + 2 * ty;        // global Q row (pair)
    if (LOGITS) {
        const float qb0 = g_qb[r0], qb1 = g_qb[r0 + 1];
        const int c0 = blockIdx.x * TILE_N;
        const float fr0 = (float)r0, fr1 = (float)(r0 + 1);
        #pragma unroll
        for (int j = 0; j < NJ; j++) {
            float2 v = unpack2(acc[j]);
            int col = c0 + tx + 16 * j;
            size_t o0 = (size_t)r0 * CTX_PER + col;
            size_t o1 = o0 + CTX_PER;
            out[o0] = v.x + qb0;
            out[o1] = v.y + qb1;
            if (rows_out) { rows_out[o0] = fr0; rows_out[o1] = fr1; }
        }
    } else {
        const int c0 = blockIdx.x * TILE_N;
        #pragma unroll
        for (int j = 0; j < NJ; j++) {
            float2 v = unpack2(acc[j]);
            int col = c0 + tx + 16 * j;
            g_Qp[(size_t)r0 * D_MODEL + col]       = v.x;
            g_Qp[(size_t)(r0 + 1) * D_MODEL + col] = v.y;
        }
    }
}

// ---------------------------------------------------------------------------
// qb[r] = arg[r,:] . b   (512 dots of 128; trivial)
// ---------------------------------------------------------------------------
__global__ void qb_kernel(const float* __restrict__ A, const float* __restrict__ b) {
    int r = blockIdx.x * blockDim.x + threadIdx.x;
    if (r < N_ARGS) {
        float s = 0.f;
        #pragma unroll
        for (int k = 0; k < KEY_DIM / 4; k++) {
            float4 a  = *(const float4*)(A + (size_t)r * KEY_DIM + 4 * k);
            float4 bb = *(const float4*)(b + 4 * k);
            s = fmaf(a.x, bb.x, s); s = fmaf(a.y, bb.y, s);
            s = fmaf(a.z, bb.z, s); s = fmaf(a.w, bb.w, s);
        }
        g_qb[r] = s;
    }
}

// ---------------------------------------------------------------------------
extern "C" void kernel_launch(void* const* d_in, const int* in_sizes, int n_in,
                              void* d_out, int out_size) {
    // Identify inputs by element count (arg_values and W share 65536 ->
    // disambiguated by order: arg_values precedes W in the input dict).
    const float* argv = nullptr;
    const float* ctxv = nullptr;
    const float* Wm   = nullptr;
    const float* bv   = nullptr;
    int seen_65536 = 0;
    for (int i = 0; i < n_in; i++) {
        long sz = in_sizes[i];
        if (sz == (long)N_CTX * D_MODEL) {
            ctxv = (const float*)d_in[i];
        } else if (sz == (long)N_ARGS * KEY_DIM) {   // == D_MODEL*KEY_DIM too
            if (seen_65536++ == 0) argv = (const float*)d_in[i];
            else                   Wm   = (const float*)d_in[i];
        } else if (sz == KEY_DIM) {
            bv = (const float*)d_in[i];
        }
    }

    float* out        = (float*)d_out;
    float* rows_out   = nullptr;
    float* logits_out = out;
    if (out_size >= 2 * P_TOT) {        // (rows, logits) concatenated
        rows_out   = out;
        logits_out = out + P_TOT;
    }

    qb_kernel<<<2, 256>>>(argv, bv);

    // Qp = arg @ W^T : M=512(16 row tiles), N=512(16 col tiles of 32), K=128
    gemm_kernel<KEY_DIM, 32, false><<<dim3(16, 16), 256>>>(
        argv, Wm, nullptr, nullptr);

    // logits: per state (blockIdx.y): [32,1024] = Qp_s @ C_s^T, 16 col tiles of 64
    gemm_kernel<D_MODEL, 64, true><<<dim3(16, 16), 256>>>(
        nullptr, ctxv, logits_out, rows_out);
}

// round 5
// speedup vs baseline: 2.9893x; 2.9893x over previous
#include <cuda_runtime.h>
#include <cstdint>

#define D_MODEL 512
#define KEY_DIM 128
#define BS_N 16
#define CTX_PER 1024
#define ARGS_PER 32
#define N_ARGS (BS_N * ARGS_PER)      /* 512  */
#define N_CTX  (BS_N * CTX_PER)       /* 16384 */
#define P_TOT  (N_ARGS * CTX_PER)     /* 524288 */

// Scratch (allocation-free rule: device globals). Accessed ONLY from device
// code -- host-side references give the host shadow symbol (R3 bug).
__device__ float g_Qp[N_ARGS * D_MODEL];   // Qp[r,d] = sum_k arg[r,k] * W[d,k]
__device__ float g_qb[N_ARGS];             // qb[r]   = arg[r,:] . b

// ---------------------------------------------------------------------------
__device__ __forceinline__ uint32_t f2tf32(float f) {
    uint32_t r;
    asm("cvt.rna.tf32.f32 %0, %1;" : "=r"(r) : "f"(f));
    return r;
}

// D(16x8) += A(16x8,row) * B(8x8,col)   tf32 inputs, fp32 accum
__device__ __forceinline__ void mma_tf32(float (&d)[4], const uint32_t (&a)[4],
                                         uint32_t b0, uint32_t b1) {
    asm volatile(
        "mma.sync.aligned.m16n8k8.row.col.f32.tf32.tf32.f32 "
        "{%0,%1,%2,%3}, {%4,%5,%6,%7}, {%8,%9}, {%0,%1,%2,%3};"
        : "+f"(d[0]), "+f"(d[1]), "+f"(d[2]), "+f"(d[3])
        : "r"(a[0]), "r"(a[1]), "r"(a[2]), "r"(a[3]), "r"(b0), "r"(b1));
}

// ---------------------------------------------------------------------------
// Tensor-core GEMM: D[32 x 128] tile of Qrows[32,KD] @ Crows[128,KD]^T
//   256 threads = 8 warps; warp w owns cols [16w, 16w+16) as two n8 tiles,
//   both m16 tiles (rows 0-31). K chunked by 32, double-buffered smem with
//   tf32 pre-converted operands. Stride-36 rows -> conflict-free frag loads.
// LOGITS: Q = g_Qp, adds g_qb, writes logits + rows planes (stride 1024).
// !LOGITS (qp): Q = arg_values, C = W, writes g_Qp (stride 512);
//               blockIdx.x==0 also computes g_qb (quad-shuffle reduction).
// ---------------------------------------------------------------------------
template<int KD, bool LOGITS>
__global__ __launch_bounds__(256) void gemm_tc(const float* __restrict__ Qm,
                                               const float* __restrict__ Cm,
                                               const float* __restrict__ bv,
                                               float* __restrict__ out,
                                               float* __restrict__ rows_out) {
    constexpr int NCH  = KD / 32;                   // K chunks
    constexpr int OSTR = LOGITS ? CTX_PER : D_MODEL;

    __shared__ uint32_t Qs[2][32][36];
    __shared__ uint32_t Cs[2][128][36];

    const int tid  = threadIdx.x;
    const int lane = tid & 31;
    const int warp = tid >> 5;
    const int qr   = lane >> 2;      // fragment groupID  (0..7)
    const int qc   = lane & 3;       // fragment threadID (0..3)

    const float* Qbase = LOGITS ? (const float*)g_Qp : Qm;
    const int qrow_base = blockIdx.y * 32;
    const int crow_base = (LOGITS ? blockIdx.y * CTX_PER : 0) + blockIdx.x * 128;
    const int ocol_base = blockIdx.x * 128;

    // loader indices
    const int lq_row = tid >> 3;                 // 0..31
    const int lq_k   = (tid & 7) * 4;            // 0..28
    const float* qsrc = Qbase + (size_t)(qrow_base + lq_row) * KD + lq_k;

    int lc_row[4], lc_k[4];
    const float* csrc[4];
    #pragma unroll
    for (int j = 0; j < 4; j++) {
        int id = tid + j * 256;
        lc_row[j] = id >> 3;                     // 0..127
        lc_k[j]   = (id & 7) * 4;
        csrc[j] = Cm + (size_t)(crow_base + lc_row[j]) * KD + lc_k[j];
    }

    float acc[2][2][4] = {};                     // [m-tile][n-tile][frag]

    // ---- prologue: chunk 0 -> buffer 0
    {
        float4 q = *(const float4*)qsrc;
        uint4 qu = make_uint4(f2tf32(q.x), f2tf32(q.y), f2tf32(q.z), f2tf32(q.w));
        *(uint4*)&Qs[0][lq_row][lq_k] = qu;
        #pragma unroll
        for (int j = 0; j < 4; j++) {
            float4 c = *(const float4*)csrc[j];
            uint4 cu = make_uint4(f2tf32(c.x), f2tf32(c.y), f2tf32(c.z), f2tf32(c.w));
            *(uint4*)&Cs[0][lc_row[j]][lc_k[j]] = cu;
        }
    }
    __syncthreads();

    const int nbase = warp * 16;

    #pragma unroll 1
    for (int it = 0; it < NCH; it++) {
        const int buf = it & 1;

        // prefetch next chunk to registers
        float4 qn;
        float4 cn[4];
        if (it + 1 < NCH) {
            qn = *(const float4*)(qsrc + (it + 1) * 32);
            #pragma unroll
            for (int j = 0; j < 4; j++)
                cn[j] = *(const float4*)(csrc[j] + (it + 1) * 32);
        }

        // compute current chunk: 4 k8 steps
        #pragma unroll
        for (int k8 = 0; k8 < 4; k8++) {
            const int kb = k8 * 8;
            uint32_t a[2][4];
            #pragma unroll
            for (int mt = 0; mt < 2; mt++) {
                a[mt][0] = Qs[buf][mt * 16 + qr    ][kb + qc];
                a[mt][1] = Qs[buf][mt * 16 + qr + 8][kb + qc];
                a[mt][2] = Qs[buf][mt * 16 + qr    ][kb + qc + 4];
                a[mt][3] = Qs[buf][mt * 16 + qr + 8][kb + qc + 4];
            }
            #pragma unroll
            for (int nt = 0; nt < 2; nt++) {
                uint32_t b0 = Cs[buf][nbase + nt * 8 + qr][kb + qc];
                uint32_t b1 = Cs[buf][nbase + nt * 8 + qr][kb + qc + 4];
                mma_tf32(acc[0][nt], a[0], b0, b1);
                mma_tf32(acc[1][nt], a[1], b0, b1);
            }
        }

        // store next chunk into other buffer
        if (it + 1 < NCH) {
            const int nb = buf ^ 1;
            uint4 qu = make_uint4(f2tf32(qn.x), f2tf32(qn.y), f2tf32(qn.z), f2tf32(qn.w));
            *(uint4*)&Qs[nb][lq_row][lq_k] = qu;
            #pragma unroll
            for (int j = 0; j < 4; j++) {
                uint4 cu = make_uint4(f2tf32(cn[j].x), f2tf32(cn[j].y),
                                      f2tf32(cn[j].z), f2tf32(cn[j].w));
                *(uint4*)&Cs[nb][lc_row[j]][lc_k[j]] = cu;
            }
            __syncthreads();
        }
    }

    // ---- epilogue
    #pragma unroll
    for (int mt = 0; mt < 2; mt++) {
        #pragma unroll
        for (int half = 0; half < 2; half++) {
            const int R  = mt * 16 + qr + half * 8;
            const int rg = qrow_base + R;             // global Q row
            const float qb = LOGITS ? g_qb[rg] : 0.0f;
            #pragma unroll
            for (int nt = 0; nt < 2; nt++) {
                const int col = ocol_base + nbase + nt * 8 + qc * 2;
                const size_t off = (size_t)rg * OSTR + col;
                float v0 = acc[mt][nt][half * 2 + 0] + qb;
                float v1 = acc[mt][nt][half * 2 + 1] + qb;
                if (LOGITS) {
                    *(float2*)(out + off) = make_float2(v0, v1);
                    if (rows_out) {
                        float fr = (float)rg;
                        *(float2*)(rows_out + off) = make_float2(fr, fr);
                    }
                } else {
                    *(float2*)(g_Qp + off) = make_float2(v0, v1);
                }
            }
        }
    }

    // ---- fused qb (qp kernel only, one column of blocks)
    if (!LOGITS && blockIdx.x == 0 && tid < 128) {
        const int row = qrow_base + (tid >> 2);
        const int seg = tid & 3;
        const float* ap = Qm + (size_t)row * KEY_DIM + seg * 32;
        const float* bp = bv + seg * 32;
        float s = 0.f;
        #pragma unroll
        for (int k = 0; k < 8; k++) {
            float4 a  = *(const float4*)(ap + 4 * k);
            float4 bb = *(const float4*)(bp + 4 * k);
            s = fmaf(a.x, bb.x, s); s = fmaf(a.y, bb.y, s);
            s = fmaf(a.z, bb.z, s); s = fmaf(a.w, bb.w, s);
        }
        s += __shfl_xor_sync(0xffffffffu, s, 1);
        s += __shfl_xor_sync(0xffffffffu, s, 2);
        if (seg == 0) g_qb[row] = s;
    }
}

// ---------------------------------------------------------------------------
extern "C" void kernel_launch(void* const* d_in, const int* in_sizes, int n_in,
                              void* d_out, int out_size) {
    // Identify inputs by element count (arg_values and W share 65536 ->
    // disambiguated by order: arg_values precedes W in the input dict).
    const float* argv = nullptr;
    const float* ctxv = nullptr;
    const float* Wm   = nullptr;
    const float* bv   = nullptr;
    int seen_65536 = 0;
    for (int i = 0; i < n_in; i++) {
        long sz = in_sizes[i];
        if (sz == (long)N_CTX * D_MODEL) {
            ctxv = (const float*)d_in[i];
        } else if (sz == (long)N_ARGS * KEY_DIM) {   // == D_MODEL*KEY_DIM too
            if (seen_65536++ == 0) argv = (const float*)d_in[i];
            else                   Wm   = (const float*)d_in[i];
        } else if (sz == KEY_DIM) {
            bv = (const float*)d_in[i];
        }
    }

    float* out        = (float*)d_out;
    float* rows_out   = nullptr;
    float* logits_out = out;
    if (out_size >= 2 * P_TOT) {        // (rows, logits) concatenated
        rows_out   = out;
        logits_out = out + P_TOT;
    }

    // Qp = arg @ W^T (+ fused qb): M=512 rows (16 y-tiles of 32),
    // N=512 dims (4 x-tiles of 128), K=128
    gemm_tc<KEY_DIM, false><<<dim3(4, 16), 256>>>(argv, Wm, bv, nullptr, nullptr);

    // logits: per state (blockIdx.y): [32,1024] = Qp_s @ C_s^T + qb,
    // 8 x-tiles of 128 cols, K=512
    gemm_tc<D_MODEL, true><<<dim3(8, 16), 256>>>(nullptr, ctxv, nullptr,
                                                 logits_out, rows_out);
}